// round 13
// baseline (speedup 1.0000x reference)
#include <cuda_runtime.h>
#include <cuda_fp16.h>
#include <cstdint>
#include <cstddef>

#define S_LEN 4096
#define BATCH 8
#define DDIM  1024
#define HDIM  1024
#define MROWS (BATCH * S_LEN)   // 32768
#define NCHUNK 32
#define CHLEN  128              // S_LEN / NCHUNK

// ---------------- scratch (device globals; no allocations allowed) ----------
__device__ __half g_z[(size_t)MROWS * HDIM];                // sigmoid(x@Wz^T+bz)
__device__ __half g_g[(size_t)MROWS * HDIM];                // g(x@Wh^T+bh)
__device__ __half g_x16[(size_t)MROWS * DDIM];
__device__ __half g_wz16[(size_t)HDIM * DDIM];
__device__ __half g_wh16[(size_t)HDIM * DDIM];
__device__ float g_A[(size_t)BATCH * NCHUNK * HDIM];        // per-chunk prod(a)
__device__ float g_B[(size_t)BATCH * NCHUNK * HDIM];        // per-chunk h | h0=0

// ---------------- helpers ----------------------------------------------------
__device__ __forceinline__ uint32_t smem_u32(const void* p) {
    uint32_t a;
    asm("{ .reg .u64 t; cvta.to.shared.u64 t, %1; cvt.u32.u64 %0, t; }"
        : "=r"(a) : "l"(p));
    return a;
}
__device__ __forceinline__ void cp_async16(uint32_t dst, const void* src) {
    asm volatile("cp.async.cg.shared.global [%0], [%1], 16;"
                 :: "r"(dst), "l"(src) : "memory");
}
__device__ __forceinline__ void cp_commit() {
    asm volatile("cp.async.commit_group;" ::: "memory");
}
template <int N>
__device__ __forceinline__ void cp_wait() {
    asm volatile("cp.async.wait_group %0;" :: "n"(N) : "memory");
}
__device__ __forceinline__ void ldsm_x4(uint32_t& r0, uint32_t& r1,
                                        uint32_t& r2, uint32_t& r3, uint32_t addr) {
    asm volatile("ldmatrix.sync.aligned.m8n8.x4.shared.b16 {%0,%1,%2,%3}, [%4];"
                 : "=r"(r0), "=r"(r1), "=r"(r2), "=r"(r3) : "r"(addr));
}
__device__ __forceinline__ void mma16816(float* d, const uint32_t* a, const uint32_t* b) {
    asm volatile(
        "mma.sync.aligned.m16n8k16.row.col.f32.f16.f16.f32 "
        "{%0,%1,%2,%3}, {%4,%5,%6,%7}, {%8,%9}, {%0,%1,%2,%3};"
        : "+f"(d[0]), "+f"(d[1]), "+f"(d[2]), "+f"(d[3])
        : "r"(a[0]), "r"(a[1]), "r"(a[2]), "r"(a[3]), "r"(b[0]), "r"(b[1]));
}
__device__ __forceinline__ uint32_t sw128(uint32_t off) {
    return off ^ ((off >> 3) & 0x70);
}

__device__ __forceinline__ float sigf(float x) { return 1.f / (1.f + __expf(-x)); }
__device__ __forceinline__ float gfun(float x) { return (x >= 0.f) ? (x + 0.5f) : sigf(x); }

// ---------------- fp32 -> fp16 convert (one launch) --------------------------
#define X_N4  (MROWS * DDIM / 4)     // 8388608
#define W_N4  (HDIM * DDIM / 4)      // 262144
__global__ void convert_all(const float* __restrict__ x,
                            const float* __restrict__ Wz,
                            const float* __restrict__ Wh)
{
    int i = blockIdx.x * blockDim.x + threadIdx.x;
    const float* src;
    __half* dst;
    int idx;
    if (i < X_N4)                 { src = x;  dst = g_x16;  idx = i; }
    else if (i < X_N4 + W_N4)     { src = Wz; dst = g_wz16; idx = i - X_N4; }
    else if (i < X_N4 + 2 * W_N4) { src = Wh; dst = g_wh16; idx = i - X_N4 - W_N4; }
    else return;
    float4 v = ((const float4*)src)[idx];
    __half2* dp = (__half2*)(dst + (size_t)idx * 4);
    dp[0] = __halves2half2(__float2half_rn(v.x), __float2half_rn(v.y));
    dp[1] = __halves2half2(__float2half_rn(v.z), __float2half_rn(v.w));
}

// ---------------- HMMA GEMM (fp16 in, fp32 accum) + fused nonlinearity -------
// z-jobs store g_z = sigmoid(X@Wz^T+bz) fp16; h-jobs store g_g = g(X@Wh^T+bh).
// Epilogue is smem-staged -> coalesced uint4 stores (R10-proven free); the
// MUFU burst overlaps the co-resident CTA's MMA mainloop (2 CTAs/SM).
// CTA 128x128, 8 warps 2(m) x 4(n), warp tile 64x32. K-chunk 64, SW128.
// 3-stage cp.async pipeline. K=1024 -> 16 chunks.
#define KCH 64
#define NITER 16
#define STAGE_BYTES 32768
#define TSTRIDE 136   // halves per staged tile row (128 + 8 pad)

__global__ void __launch_bounds__(256)
gemm_mma(const float* __restrict__ bz, const float* __restrict__ bh)
{
    __shared__ __align__(1024) uint8_t smem[3 * STAGE_BYTES];

    const int tid = threadIdx.x, wid = tid >> 5, lane = tid & 31;
    const int wm = wid >> 2, wn = wid & 3;     // 2 x 4 warp grid
    const bool is_z = (blockIdx.x < 8);
    const int n0 = (is_z ? blockIdx.x : blockIdx.x - 8) * 128;
    const int m0 = blockIdx.y * 128;
    const __half* W = is_z ? g_wz16 : g_wh16;
    const float* bias = is_z ? bz : bh;
    __half* C = is_z ? g_z : g_g;

    const uint32_t sbase = smem_u32(smem);

    float acc[4][4][4];   // [mi][nj][frag]
#pragma unroll
    for (int i = 0; i < 4; i++)
#pragma unroll
        for (int j = 0; j < 4; j++)
#pragma unroll
            for (int f = 0; f < 4; f++) acc[i][j][f] = 0.f;

    auto issue = [&](int ch, int st) {
        const int kc = ch * KCH;
        const uint32_t stb = sbase + st * STAGE_BYTES;
#pragma unroll
        for (int i = 0; i < 4; i++) {
            int s = tid + i * 256;              // 1024 slots of 16B per tile
            int row = s >> 3, kslot = s & 7;
            uint32_t off = sw128(row * 128 + kslot * 16);
            cp_async16(stb + off,
                       g_x16 + (size_t)(m0 + row) * DDIM + kc + kslot * 8);
            cp_async16(stb + 16384 + off,
                       W + (size_t)(n0 + row) * DDIM + kc + kslot * 8);
        }
        cp_commit();
    };

    issue(0, 0);
    issue(1, 1);

    int st = 0;
    for (int ch = 0; ch < NITER; ch++) {
        if (ch + 2 < NITER) cp_wait<1>(); else cp_wait<0>();
        __syncthreads();
        if (ch + 2 < NITER) issue(ch + 2, (st + 2) % 3);

        const uint32_t aB = sbase + st * STAGE_BYTES;
        const uint32_t bB = aB + 16384;

#pragma unroll
        for (int ks = 0; ks < 4; ks++) {        // 4 x k16 per chunk
            uint32_t af[4][4], bf[2][4];
#pragma unroll
            for (int mi = 0; mi < 4; mi++) {
                int row = wm * 64 + mi * 16 + (lane & 15);
                uint32_t off = sw128(row * 128 + ks * 32 + (lane >> 4) * 16);
                ldsm_x4(af[mi][0], af[mi][1], af[mi][2], af[mi][3], aB + off);
            }
#pragma unroll
            for (int bj = 0; bj < 2; bj++) {
                int row = wn * 32 + bj * 16 + (lane & 7) + ((lane >> 4) & 1) * 8;
                uint32_t off = sw128(row * 128 + ks * 32 + ((lane >> 3) & 1) * 16);
                ldsm_x4(bf[bj][0], bf[bj][1], bf[bj][2], bf[bj][3], bB + off);
            }
#pragma unroll
            for (int mi = 0; mi < 4; mi++) {
#pragma unroll
                for (int bj = 0; bj < 2; bj++) {
                    mma16816(acc[mi][bj * 2],     af[mi], &bf[bj][0]);
                    mma16816(acc[mi][bj * 2 + 1], af[mi], &bf[bj][2]);
                }
            }
        }
        st = (st + 1) % 3;
    }

    // ---- epilogue: bias + nonlinearity -> fp16 -> smem stage -> uint4 stores
    __syncthreads();
    __half* tile = (__half*)smem;   // 128 x TSTRIDE halves = 34 KB
#pragma unroll
    for (int mi = 0; mi < 4; mi++) {
#pragma unroll
        for (int nj = 0; nj < 4; nj++) {
            int r = wm * 64 + mi * 16 + (lane >> 2);
            int c = wn * 32 + nj * 8 + (lane & 3) * 2;
            float2 bv = *(const float2*)(bias + n0 + c);
            float v[4] = {acc[mi][nj][0] + bv.x, acc[mi][nj][1] + bv.y,
                          acc[mi][nj][2] + bv.x, acc[mi][nj][3] + bv.y};
            float r4[4];
            if (is_z) {
#pragma unroll
                for (int f = 0; f < 4; f++) r4[f] = sigf(v[f]);
            } else {
#pragma unroll
                for (int f = 0; f < 4; f++) r4[f] = gfun(v[f]);
            }
            *(__half2*)(tile + r * TSTRIDE + c) = __floats2half2_rn(r4[0], r4[1]);
            *(__half2*)(tile + (r + 8) * TSTRIDE + c) = __floats2half2_rn(r4[2], r4[3]);
        }
    }
    __syncthreads();
#pragma unroll
    for (int it = 0; it < 8; it++) {
        int id = tid + it * 256;            // 2048 chunks of 8 halves
        int row = id >> 4, c8 = (id & 15) * 8;
        uint4 v = *(const uint4*)(tile + row * TSTRIDE + c8);
        *(uint4*)(C + (size_t)(m0 + row) * HDIM + n0 + c8) = v;
    }
}

// ---------------- scan: h_t = (1-z_t) h_{t-1} + z_t g_t ----------------------
// Pure FMA now (nonlinearity lives in the gemm epilogue).
// 2 channels per thread, half2 loads, 1024 CTAs (R10-proven config).
__global__ void scan_p1()
{
    const int h  = (blockIdx.x * 128 + threadIdx.x) * 2;
    const int ch = blockIdx.y;
    const int b  = blockIdx.z;
    const size_t base = ((size_t)(b * S_LEN + ch * CHLEN)) * HDIM + h;
    const __half* zp = g_z + base;
    const __half* gp = g_g + base;
    float A0 = 1.f, A1 = 1.f, B0 = 0.f, B1 = 0.f;
    for (int s0 = 0; s0 < CHLEN; s0 += 8) {
        __half2 zz[8], gg[8];
#pragma unroll
        for (int j = 0; j < 8; j++) {
            zz[j] = *(const __half2*)(zp + (size_t)(s0 + j) * HDIM);
            gg[j] = *(const __half2*)(gp + (size_t)(s0 + j) * HDIM);
        }
#pragma unroll
        for (int j = 0; j < 8; j++) {
            float2 zv = __half22float2(zz[j]);
            float2 gv = __half22float2(gg[j]);
            float a0 = 1.f - zv.x, a1 = 1.f - zv.y;
            B0 = fmaf(a0, B0, zv.x * gv.x);
            B1 = fmaf(a1, B1, zv.y * gv.y);
            A0 *= a0; A1 *= a1;
        }
    }
    const size_t ci = ((size_t)(b * NCHUNK + ch)) * HDIM + h;
    *(float2*)(g_A + ci) = make_float2(A0, A1);
    *(float2*)(g_B + ci) = make_float2(B0, B1);
}

// pass 2 folded into pass 3: rebuild chunk-prefix from g_A/g_B (L2-hot), then
// re-run the chunk emitting outputs.
__global__ void scan_p3(const float* __restrict__ h0, float* __restrict__ out)
{
    const int h  = (blockIdx.x * 128 + threadIdx.x) * 2;
    const int ch = blockIdx.y;
    const int b  = blockIdx.z;

    float2 x0 = *(const float2*)(h0 + b * HDIM + h);
    float h0c = gfun(x0.x), h1c = gfun(x0.y);
    for (int c = 0; c < ch; c++) {
        const size_t ci = ((size_t)(b * NCHUNK + c)) * HDIM + h;
        float2 Av = *(const float2*)(g_A + ci);
        float2 Bv = *(const float2*)(g_B + ci);
        h0c = fmaf(Av.x, h0c, Bv.x);
        h1c = fmaf(Av.y, h1c, Bv.y);
    }

    const size_t base = ((size_t)(b * S_LEN + ch * CHLEN)) * HDIM + h;
    const __half* zp = g_z + base;
    const __half* gp = g_g + base;
    float* op = out + base;
    for (int s0 = 0; s0 < CHLEN; s0 += 8) {
        __half2 zz[8], gg[8];
#pragma unroll
        for (int j = 0; j < 8; j++) {
            zz[j] = *(const __half2*)(zp + (size_t)(s0 + j) * HDIM);
            gg[j] = *(const __half2*)(gp + (size_t)(s0 + j) * HDIM);
        }
#pragma unroll
        for (int j = 0; j < 8; j++) {
            float2 zv = __half22float2(zz[j]);
            float2 gv = __half22float2(gg[j]);
            h0c = fmaf(zv.x, gv.x - h0c, h0c);
            h1c = fmaf(zv.y, gv.y - h1c, h1c);
            *(float2*)(op + (size_t)(s0 + j) * HDIM) = make_float2(h0c, h1c);
        }
    }
}

// ---------------- launch ------------------------------------------------------
extern "C" void kernel_launch(void* const* d_in, const int* in_sizes, int n_in,
                              void* d_out, int out_size)
{
    const float* x  = (const float*)d_in[0];
    const float* h0 = (const float*)d_in[1];
    const float* Wz = (const float*)d_in[2];
    const float* bz = (const float*)d_in[3];
    const float* Wh = (const float*)d_in[4];
    const float* bh = (const float*)d_in[5];
    float* out = (float*)d_out;

    convert_all<<<(X_N4 + 2 * W_N4 + 255) / 256, 256>>>(x, Wz, Wh);

    dim3 ggrid(16, MROWS / 128);
    gemm_mma<<<ggrid, 256>>>(bz, bh);

    dim3 sgrid(HDIM / 256, NCHUNK, BATCH);   // 2 channels per thread, 1024 CTAs
    scan_p1<<<sgrid, 128>>>();
    scan_p3<<<sgrid, 128>>>(h0, out);
}

// round 14
// speedup vs baseline: 1.4061x; 1.4061x over previous
#include <cuda_runtime.h>
#include <cuda_fp16.h>
#include <cstdint>
#include <cstddef>

#define S_LEN 4096
#define BATCH 8
#define DDIM  1024
#define HDIM  1024
#define MROWS (BATCH * S_LEN)   // 32768
#define NCHUNK 32
#define CHLEN  128              // S_LEN / NCHUNK

// ---------------- scratch (device globals; no allocations allowed) ----------
__device__ __half g_z[(size_t)MROWS * HDIM];                // sigmoid(x@Wz^T+bz)
__device__ __half g_g[(size_t)MROWS * HDIM];                // g(x@Wh^T+bh)
__device__ __half g_x16[(size_t)MROWS * DDIM];
__device__ __half g_wz16[(size_t)HDIM * DDIM];
__device__ __half g_wh16[(size_t)HDIM * DDIM];
__device__ float g_A[(size_t)BATCH * NCHUNK * HDIM];        // per-chunk prod(a)
__device__ float g_B[(size_t)BATCH * NCHUNK * HDIM];        // per-chunk h | h0=0

// ---------------- helpers ----------------------------------------------------
__device__ __forceinline__ uint32_t smem_u32(const void* p) {
    uint32_t a;
    asm("{ .reg .u64 t; cvta.to.shared.u64 t, %1; cvt.u32.u64 %0, t; }"
        : "=r"(a) : "l"(p));
    return a;
}
__device__ __forceinline__ void cp_async16(uint32_t dst, const void* src) {
    asm volatile("cp.async.cg.shared.global [%0], [%1], 16;"
                 :: "r"(dst), "l"(src) : "memory");
}
__device__ __forceinline__ void cp_commit() {
    asm volatile("cp.async.commit_group;" ::: "memory");
}
template <int N>
__device__ __forceinline__ void cp_wait() {
    asm volatile("cp.async.wait_group %0;" :: "n"(N) : "memory");
}
__device__ __forceinline__ void ldsm_x4(uint32_t& r0, uint32_t& r1,
                                        uint32_t& r2, uint32_t& r3, uint32_t addr) {
    asm volatile("ldmatrix.sync.aligned.m8n8.x4.shared.b16 {%0,%1,%2,%3}, [%4];"
                 : "=r"(r0), "=r"(r1), "=r"(r2), "=r"(r3) : "r"(addr));
}
__device__ __forceinline__ void mma16816(float* d, const uint32_t* a, const uint32_t* b) {
    asm volatile(
        "mma.sync.aligned.m16n8k16.row.col.f32.f16.f16.f32 "
        "{%0,%1,%2,%3}, {%4,%5,%6,%7}, {%8,%9}, {%0,%1,%2,%3};"
        : "+f"(d[0]), "+f"(d[1]), "+f"(d[2]), "+f"(d[3])
        : "r"(a[0]), "r"(a[1]), "r"(a[2]), "r"(a[3]), "r"(b[0]), "r"(b[1]));
}
__device__ __forceinline__ uint32_t sw128(uint32_t off) {
    return off ^ ((off >> 3) & 0x70);
}

__device__ __forceinline__ float sigf(float x) { return 1.f / (1.f + __expf(-x)); }
__device__ __forceinline__ float gfun(float x) { return (x >= 0.f) ? (x + 0.5f) : sigf(x); }

// ---------------- fp32 -> fp16 convert (one launch) --------------------------
#define X_N4  (MROWS * DDIM / 4)     // 8388608
#define W_N4  (HDIM * DDIM / 4)      // 262144
__global__ void convert_all(const float* __restrict__ x,
                            const float* __restrict__ Wz,
                            const float* __restrict__ Wh)
{
    int i = blockIdx.x * blockDim.x + threadIdx.x;
    const float* src;
    __half* dst;
    int idx;
    if (i < X_N4)                 { src = x;  dst = g_x16;  idx = i; }
    else if (i < X_N4 + W_N4)     { src = Wz; dst = g_wz16; idx = i - X_N4; }
    else if (i < X_N4 + 2 * W_N4) { src = Wh; dst = g_wh16; idx = i - X_N4 - W_N4; }
    else return;
    float4 v = ((const float4*)src)[idx];
    __half2* dp = (__half2*)(dst + (size_t)idx * 4);
    dp[0] = __halves2half2(__float2half_rn(v.x), __float2half_rn(v.y));
    dp[1] = __halves2half2(__float2half_rn(v.z), __float2half_rn(v.w));
}

// ---------------- HMMA GEMM (fp16 in, fp32 accum) + fused nonlinearity -------
// z-jobs store g_z = sigmoid(X@Wz^T+bz) fp16; h-jobs store g_g = g(X@Wh^T+bh).
// KEY FIX vs R13: __launch_bounds__(256, 2). The R12 mainloop uses exactly
// 128 regs (= full RF at 2 CTAs/SM); R13's epilogue MUFU pushed regs past 128,
// silently dropping occupancy to 1 CTA/SM and cratering tensor duty (+220us).
// Forcing minBlocksPerSM=2 caps regs at 128; epilogue-only temps spill to
// local, off the mainloop critical path.
#define KCH 64
#define NITER 16
#define STAGE_BYTES 32768
#define TSTRIDE 136   // halves per staged tile row (128 + 8 pad)

__global__ void __launch_bounds__(256, 2)
gemm_mma(const float* __restrict__ bz, const float* __restrict__ bh)
{
    __shared__ __align__(1024) uint8_t smem[3 * STAGE_BYTES];

    const int tid = threadIdx.x, wid = tid >> 5, lane = tid & 31;
    const int wm = wid >> 2, wn = wid & 3;     // 2 x 4 warp grid
    const bool is_z = (blockIdx.x < 8);
    const int n0 = (is_z ? blockIdx.x : blockIdx.x - 8) * 128;
    const int m0 = blockIdx.y * 128;
    const __half* W = is_z ? g_wz16 : g_wh16;
    const float* bias = is_z ? bz : bh;
    __half* C = is_z ? g_z : g_g;

    const uint32_t sbase = smem_u32(smem);

    float acc[4][4][4];   // [mi][nj][frag]
#pragma unroll
    for (int i = 0; i < 4; i++)
#pragma unroll
        for (int j = 0; j < 4; j++)
#pragma unroll
            for (int f = 0; f < 4; f++) acc[i][j][f] = 0.f;

    auto issue = [&](int ch, int st) {
        const int kc = ch * KCH;
        const uint32_t stb = sbase + st * STAGE_BYTES;
#pragma unroll
        for (int i = 0; i < 4; i++) {
            int s = tid + i * 256;              // 1024 slots of 16B per tile
            int row = s >> 3, kslot = s & 7;
            uint32_t off = sw128(row * 128 + kslot * 16);
            cp_async16(stb + off,
                       g_x16 + (size_t)(m0 + row) * DDIM + kc + kslot * 8);
            cp_async16(stb + 16384 + off,
                       W + (size_t)(n0 + row) * DDIM + kc + kslot * 8);
        }
        cp_commit();
    };

    issue(0, 0);
    issue(1, 1);

    int st = 0;
    for (int ch = 0; ch < NITER; ch++) {
        if (ch + 2 < NITER) cp_wait<1>(); else cp_wait<0>();
        __syncthreads();
        if (ch + 2 < NITER) issue(ch + 2, (st + 2) % 3);

        const uint32_t aB = sbase + st * STAGE_BYTES;
        const uint32_t bB = aB + 16384;

#pragma unroll
        for (int ks = 0; ks < 4; ks++) {        // 4 x k16 per chunk
            uint32_t af[4][4], bf[2][4];
#pragma unroll
            for (int mi = 0; mi < 4; mi++) {
                int row = wm * 64 + mi * 16 + (lane & 15);
                uint32_t off = sw128(row * 128 + ks * 32 + (lane >> 4) * 16);
                ldsm_x4(af[mi][0], af[mi][1], af[mi][2], af[mi][3], aB + off);
            }
#pragma unroll
            for (int bj = 0; bj < 2; bj++) {
                int row = wn * 32 + bj * 16 + (lane & 7) + ((lane >> 4) & 1) * 8;
                uint32_t off = sw128(row * 128 + ks * 32 + ((lane >> 3) & 1) * 16);
                ldsm_x4(bf[bj][0], bf[bj][1], bf[bj][2], bf[bj][3], bB + off);
            }
#pragma unroll
            for (int mi = 0; mi < 4; mi++) {
#pragma unroll
                for (int bj = 0; bj < 2; bj++) {
                    mma16816(acc[mi][bj * 2],     af[mi], &bf[bj][0]);
                    mma16816(acc[mi][bj * 2 + 1], af[mi], &bf[bj][2]);
                }
            }
        }
        st = (st + 1) % 3;
    }

    // ---- epilogue: bias + nonlinearity -> fp16 -> smem stage -> uint4 stores
    __syncthreads();
    __half* tile = (__half*)smem;   // 128 x TSTRIDE halves = 34 KB
#pragma unroll
    for (int mi = 0; mi < 4; mi++) {
#pragma unroll
        for (int nj = 0; nj < 4; nj++) {
            int r = wm * 64 + mi * 16 + (lane >> 2);
            int c = wn * 32 + nj * 8 + (lane & 3) * 2;
            float2 bv = *(const float2*)(bias + n0 + c);
            float v[4] = {acc[mi][nj][0] + bv.x, acc[mi][nj][1] + bv.y,
                          acc[mi][nj][2] + bv.x, acc[mi][nj][3] + bv.y};
            float r4[4];
            if (is_z) {
#pragma unroll
                for (int f = 0; f < 4; f++) r4[f] = sigf(v[f]);
            } else {
#pragma unroll
                for (int f = 0; f < 4; f++) r4[f] = gfun(v[f]);
            }
            *(__half2*)(tile + r * TSTRIDE + c) = __floats2half2_rn(r4[0], r4[1]);
            *(__half2*)(tile + (r + 8) * TSTRIDE + c) = __floats2half2_rn(r4[2], r4[3]);
        }
    }
    __syncthreads();
#pragma unroll
    for (int it = 0; it < 8; it++) {
        int id = tid + it * 256;            // 2048 chunks of 8 halves
        int row = id >> 4, c8 = (id & 15) * 8;
        uint4 v = *(const uint4*)(tile + row * TSTRIDE + c8);
        *(uint4*)(C + (size_t)(m0 + row) * HDIM + n0 + c8) = v;
    }
}

// ---------------- scan: h_t = (1-z_t) h_{t-1} + z_t g_t ----------------------
// Pure FMA (nonlinearity lives in the gemm epilogue).
// 2 channels per thread, half2 loads, 1024 CTAs.
__global__ void scan_p1()
{
    const int h  = (blockIdx.x * 128 + threadIdx.x) * 2;
    const int ch = blockIdx.y;
    const int b  = blockIdx.z;
    const size_t base = ((size_t)(b * S_LEN + ch * CHLEN)) * HDIM + h;
    const __half* zp = g_z + base;
    const __half* gp = g_g + base;
    float A0 = 1.f, A1 = 1.f, B0 = 0.f, B1 = 0.f;
    for (int s0 = 0; s0 < CHLEN; s0 += 8) {
        __half2 zz[8], gg[8];
#pragma unroll
        for (int j = 0; j < 8; j++) {
            zz[j] = *(const __half2*)(zp + (size_t)(s0 + j) * HDIM);
            gg[j] = *(const __half2*)(gp + (size_t)(s0 + j) * HDIM);
        }
#pragma unroll
        for (int j = 0; j < 8; j++) {
            float2 zv = __half22float2(zz[j]);
            float2 gv = __half22float2(gg[j]);
            float a0 = 1.f - zv.x, a1 = 1.f - zv.y;
            B0 = fmaf(a0, B0, zv.x * gv.x);
            B1 = fmaf(a1, B1, zv.y * gv.y);
            A0 *= a0; A1 *= a1;
        }
    }
    const size_t ci = ((size_t)(b * NCHUNK + ch)) * HDIM + h;
    *(float2*)(g_A + ci) = make_float2(A0, A1);
    *(float2*)(g_B + ci) = make_float2(B0, B1);
}

// pass 2 folded into pass 3: rebuild chunk-prefix from g_A/g_B (L2-hot), then
// re-run the chunk emitting outputs.
__global__ void scan_p3(const float* __restrict__ h0, float* __restrict__ out)
{
    const int h  = (blockIdx.x * 128 + threadIdx.x) * 2;
    const int ch = blockIdx.y;
    const int b  = blockIdx.z;

    float2 x0 = *(const float2*)(h0 + b * HDIM + h);
    float h0c = gfun(x0.x), h1c = gfun(x0.y);
    for (int c = 0; c < ch; c++) {
        const size_t ci = ((size_t)(b * NCHUNK + c)) * HDIM + h;
        float2 Av = *(const float2*)(g_A + ci);
        float2 Bv = *(const float2*)(g_B + ci);
        h0c = fmaf(Av.x, h0c, Bv.x);
        h1c = fmaf(Av.y, h1c, Bv.y);
    }

    const size_t base = ((size_t)(b * S_LEN + ch * CHLEN)) * HDIM + h;
    const __half* zp = g_z + base;
    const __half* gp = g_g + base;
    float* op = out + base;
    for (int s0 = 0; s0 < CHLEN; s0 += 8) {
        __half2 zz[8], gg[8];
#pragma unroll
        for (int j = 0; j < 8; j++) {
            zz[j] = *(const __half2*)(zp + (size_t)(s0 + j) * HDIM);
            gg[j] = *(const __half2*)(gp + (size_t)(s0 + j) * HDIM);
        }
#pragma unroll
        for (int j = 0; j < 8; j++) {
            float2 zv = __half22float2(zz[j]);
            float2 gv = __half22float2(gg[j]);
            h0c = fmaf(zv.x, gv.x - h0c, h0c);
            h1c = fmaf(zv.y, gv.y - h1c, h1c);
            *(float2*)(op + (size_t)(s0 + j) * HDIM) = make_float2(h0c, h1c);
        }
    }
}

// ---------------- launch ------------------------------------------------------
extern "C" void kernel_launch(void* const* d_in, const int* in_sizes, int n_in,
                              void* d_out, int out_size)
{
    const float* x  = (const float*)d_in[0];
    const float* h0 = (const float*)d_in[1];
    const float* Wz = (const float*)d_in[2];
    const float* bz = (const float*)d_in[3];
    const float* Wh = (const float*)d_in[4];
    const float* bh = (const float*)d_in[5];
    float* out = (float*)d_out;

    convert_all<<<(X_N4 + 2 * W_N4 + 255) / 256, 256>>>(x, Wz, Wh);

    dim3 ggrid(16, MROWS / 128);
    gemm_mma<<<ggrid, 256>>>(bz, bh);

    dim3 sgrid(HDIM / 256, NCHUNK, BATCH);   // 2 channels per thread, 1024 CTAs
    scan_p1<<<sgrid, 128>>>();
    scan_p3<<<sgrid, 128>>>(h0, out);
}

// round 16
// speedup vs baseline: 1.4771x; 1.0505x over previous
#include <cuda_runtime.h>
#include <cuda_fp16.h>
#include <cstdint>
#include <cstddef>

#define S_LEN 4096
#define BATCH 8
#define DDIM  1024
#define HDIM  1024
#define MROWS (BATCH * S_LEN)   // 32768
#define NCHUNK 32
#define CHLEN  128              // S_LEN / NCHUNK

// ---------------- scratch (device globals; no allocations allowed) ----------
__device__ __half g_z[(size_t)MROWS * HDIM];                // sigmoid(x@Wz^T+bz)
__device__ __half g_g[(size_t)MROWS * HDIM];                // g(x@Wh^T+bh)
__device__ __half g_x16[(size_t)MROWS * DDIM];
__device__ __half g_wz16[(size_t)HDIM * DDIM];
__device__ __half g_wh16[(size_t)HDIM * DDIM];
__device__ float g_A[(size_t)BATCH * NCHUNK * HDIM];        // per-chunk prod(a)
__device__ float g_B[(size_t)BATCH * NCHUNK * HDIM];        // per-chunk h | h0=0

// ---------------- helpers ----------------------------------------------------
__device__ __forceinline__ uint32_t smem_u32(const void* p) {
    uint32_t a;
    asm("{ .reg .u64 t; cvta.to.shared.u64 t, %1; cvt.u32.u64 %0, t; }"
        : "=r"(a) : "l"(p));
    return a;
}
__device__ __forceinline__ void cp_async16(uint32_t dst, const void* src) {
    asm volatile("cp.async.cg.shared.global [%0], [%1], 16;"
                 :: "r"(dst), "l"(src) : "memory");
}
__device__ __forceinline__ void cp_commit() {
    asm volatile("cp.async.commit_group;" ::: "memory");
}
template <int N>
__device__ __forceinline__ void cp_wait() {
    asm volatile("cp.async.wait_group %0;" :: "n"(N) : "memory");
}
__device__ __forceinline__ void ldsm_x4(uint32_t& r0, uint32_t& r1,
                                        uint32_t& r2, uint32_t& r3, uint32_t addr) {
    asm volatile("ldmatrix.sync.aligned.m8n8.x4.shared.b16 {%0,%1,%2,%3}, [%4];"
                 : "=r"(r0), "=r"(r1), "=r"(r2), "=r"(r3) : "r"(addr));
}
__device__ __forceinline__ void mma16816(float* d, const uint32_t* a, const uint32_t* b) {
    asm volatile(
        "mma.sync.aligned.m16n8k16.row.col.f32.f16.f16.f32 "
        "{%0,%1,%2,%3}, {%4,%5,%6,%7}, {%8,%9}, {%0,%1,%2,%3};"
        : "+f"(d[0]), "+f"(d[1]), "+f"(d[2]), "+f"(d[3])
        : "r"(a[0]), "r"(a[1]), "r"(a[2]), "r"(a[3]), "r"(b[0]), "r"(b[1]));
}
__device__ __forceinline__ uint32_t sw128(uint32_t off) {
    return off ^ ((off >> 3) & 0x70);
}

__device__ __forceinline__ float sigf(float x) { return 1.f / (1.f + __expf(-x)); }
__device__ __forceinline__ float gfun(float x) { return (x >= 0.f) ? (x + 0.5f) : sigf(x); }

// ---------------- fp32 -> fp16 convert (one launch) --------------------------
#define X_N4  (MROWS * DDIM / 4)     // 8388608
#define W_N4  (HDIM * DDIM / 4)      // 262144
__global__ void convert_all(const float* __restrict__ x,
                            const float* __restrict__ Wz,
                            const float* __restrict__ Wh)
{
    int i = blockIdx.x * blockDim.x + threadIdx.x;
    const float* src;
    __half* dst;
    int idx;
    if (i < X_N4)                 { src = x;  dst = g_x16;  idx = i; }
    else if (i < X_N4 + W_N4)     { src = Wz; dst = g_wz16; idx = i - X_N4; }
    else if (i < X_N4 + 2 * W_N4) { src = Wh; dst = g_wh16; idx = i - X_N4 - W_N4; }
    else return;
    float4 v = ((const float4*)src)[idx];
    __half2* dp = (__half2*)(dst + (size_t)idx * 4);
    dp[0] = __halves2half2(__float2half_rn(v.x), __float2half_rn(v.y));
    dp[1] = __halves2half2(__float2half_rn(v.z), __float2half_rn(v.w));
}

// ---------------- dual-output HMMA GEMM + fused nonlinearity + fused p1 ------
// One CTA computes BOTH z = sigmoid(X@Wz^T+bz) and g = g(X@Wh^T+bh) for a
// 128(m) x 64(n) tile, sharing the A(x) tile. Since 128 m-rows == one scan
// chunk, the epilogue also computes the per-chunk scan state (g_A, g_B),
// eliminating the scan_p1 kernel entirely.
// 8 warps as 4(m) x 2(n); warp tile 32x32 per matrix (accs 64 = same RF as R14).
// K-chunk 64, SW128, 3-stage cp.async. __launch_bounds__(256,2): R13/R14-proven
// guard against the 128-reg occupancy cliff.
#define KCH 64
#define NITER 16
#define STAGE_BYTES 32768      // A 16KB + Bz 8KB + Bg 8KB
#define NT 64                  // n per CTA
#define TST 72                 // halves per staged row (64 + 8 pad)

__global__ void __launch_bounds__(256, 2)
gemm_mma(const float* __restrict__ bz, const float* __restrict__ bh)
{
    __shared__ __align__(1024) uint8_t smem[3 * STAGE_BYTES];

    const int tid = threadIdx.x, wid = tid >> 5, lane = tid & 31;
    const int wm = wid >> 1, wn = wid & 1;     // 4(m) x 2(n) warp grid
    const int n0 = blockIdx.x * NT;
    const int m0 = blockIdx.y * 128;

    const uint32_t sbase = smem_u32(smem);

    float az[2][4][4], ag[2][4][4];   // [mi][nj][frag] per matrix
#pragma unroll
    for (int i = 0; i < 2; i++)
#pragma unroll
        for (int j = 0; j < 4; j++)
#pragma unroll
            for (int f = 0; f < 4; f++) { az[i][j][f] = 0.f; ag[i][j][f] = 0.f; }

    auto issue = [&](int ch, int st) {
        const int kc = ch * KCH;
        const uint32_t stb = sbase + st * STAGE_BYTES;
#pragma unroll
        for (int i = 0; i < 8; i++) {
            int s = tid + i * 256;              // 2048 x 16B slots
            if (s < 1024) {                     // A: 128 rows x 8 kslots
                int row = s >> 3, kslot = s & 7;
                uint32_t off = sw128(row * 128 + kslot * 16);
                cp_async16(stb + off,
                           g_x16 + (size_t)(m0 + row) * DDIM + kc + kslot * 8);
            } else if (s < 1536) {              // Bz: 64 rows x 8 kslots
                int t = s - 1024;
                int row = t >> 3, kslot = t & 7;
                uint32_t off = sw128(row * 128 + kslot * 16);
                cp_async16(stb + 16384 + off,
                           g_wz16 + (size_t)(n0 + row) * DDIM + kc + kslot * 8);
            } else {                            // Bg
                int t = s - 1536;
                int row = t >> 3, kslot = t & 7;
                uint32_t off = sw128(row * 128 + kslot * 16);
                cp_async16(stb + 24576 + off,
                           g_wh16 + (size_t)(n0 + row) * DDIM + kc + kslot * 8);
            }
        }
        cp_commit();
    };

    issue(0, 0);
    issue(1, 1);

    int st = 0;
    for (int ch = 0; ch < NITER; ch++) {
        if (ch + 2 < NITER) cp_wait<1>(); else cp_wait<0>();
        __syncthreads();
        if (ch + 2 < NITER) issue(ch + 2, (st + 2) % 3);

        const uint32_t aB  = sbase + st * STAGE_BYTES;
        const uint32_t bBz = aB + 16384;
        const uint32_t bBg = aB + 24576;

#pragma unroll
        for (int ks = 0; ks < 4; ks++) {        // 4 x k16 per chunk
            uint32_t af[2][4], bfz[2][4], bfg[2][4];
#pragma unroll
            for (int mi = 0; mi < 2; mi++) {
                int row = wm * 32 + mi * 16 + (lane & 15);
                uint32_t off = sw128(row * 128 + ks * 32 + (lane >> 4) * 16);
                ldsm_x4(af[mi][0], af[mi][1], af[mi][2], af[mi][3], aB + off);
            }
#pragma unroll
            for (int bj = 0; bj < 2; bj++) {
                int row = wn * 32 + bj * 16 + (lane & 7) + ((lane >> 4) & 1) * 8;
                uint32_t off = sw128(row * 128 + ks * 32 + ((lane >> 3) & 1) * 16);
                ldsm_x4(bfz[bj][0], bfz[bj][1], bfz[bj][2], bfz[bj][3], bBz + off);
                ldsm_x4(bfg[bj][0], bfg[bj][1], bfg[bj][2], bfg[bj][3], bBg + off);
            }
#pragma unroll
            for (int mi = 0; mi < 2; mi++) {
#pragma unroll
                for (int bj = 0; bj < 2; bj++) {
                    mma16816(az[mi][bj * 2],     af[mi], &bfz[bj][0]);
                    mma16816(az[mi][bj * 2 + 1], af[mi], &bfz[bj][2]);
                    mma16816(ag[mi][bj * 2],     af[mi], &bfg[bj][0]);
                    mma16816(ag[mi][bj * 2 + 1], af[mi], &bfg[bj][2]);
                }
            }
        }
        st = (st + 1) % 3;
    }

    // ---- epilogue: bias + nonlinearity -> fp16 smem tiles ----
    __syncthreads();
    __half* tz = (__half*)smem;                 // 128 x TST halves = 18 KB
    __half* tg = (__half*)(smem + 18432);       // 128 x TST halves
    float* pA = (float*)(smem + 36864);         // [2][64] seg partials
    float* pB = pA + 128;
#pragma unroll
    for (int mi = 0; mi < 2; mi++) {
#pragma unroll
        for (int nj = 0; nj < 4; nj++) {
            int r = wm * 32 + mi * 16 + (lane >> 2);
            int c = wn * 32 + nj * 8 + (lane & 3) * 2;
            float2 bvz = *(const float2*)(bz + n0 + c);
            float2 bvh = *(const float2*)(bh + n0 + c);
            float z0 = sigf(az[mi][nj][0] + bvz.x), z1 = sigf(az[mi][nj][1] + bvz.y);
            float z2 = sigf(az[mi][nj][2] + bvz.x), z3 = sigf(az[mi][nj][3] + bvz.y);
            float g0 = gfun(ag[mi][nj][0] + bvh.x), g1 = gfun(ag[mi][nj][1] + bvh.y);
            float g2 = gfun(ag[mi][nj][2] + bvh.x), g3 = gfun(ag[mi][nj][3] + bvh.y);
            *(__half2*)(tz + r * TST + c)       = __floats2half2_rn(z0, z1);
            *(__half2*)(tz + (r + 8) * TST + c) = __floats2half2_rn(z2, z3);
            *(__half2*)(tg + r * TST + c)       = __floats2half2_rn(g0, g1);
            *(__half2*)(tg + (r + 8) * TST + c) = __floats2half2_rn(g2, g3);
        }
    }
    __syncthreads();

    // coalesced global stores: 128 rows x 64 halves per tile (8 uint4 / row)
#pragma unroll
    for (int it = 0; it < 4; it++) {
        int id = tid + it * 256;            // 1024 chunks of 8 halves per tile
        int row = id >> 3, c8 = (id & 7) * 8;
        *(uint4*)(g_z + (size_t)(m0 + row) * HDIM + n0 + c8) =
            *(const uint4*)(tz + row * TST + c8);
        *(uint4*)(g_g + (size_t)(m0 + row) * HDIM + n0 + c8) =
            *(const uint4*)(tg + row * TST + c8);
    }

    // fused scan_p1: per-channel (A = prod(1-z), B = scan | h=0) over 128 steps
    // 128 threads: channel c = tid>>1, segment seg = tid&1 (64 steps each)
    if (tid < 128) {
        int c = tid >> 1, seg = tid & 1;
        float A = 1.f, B = 0.f;
        int s0 = seg * 64;
#pragma unroll 8
        for (int s = 0; s < 64; s++) {
            float z = __half2float(tz[(s0 + s) * TST + c]);
            float g = __half2float(tg[(s0 + s) * TST + c]);
            float a = 1.f - z;
            B = fmaf(a, B, z * g);
            A *= a;
        }
        pA[seg * 64 + c] = A;
        pB[seg * 64 + c] = B;
    }
    __syncthreads();
    if (tid < 64) {
        int c = tid;
        float A0 = pA[c], B0 = pB[c], A1 = pA[64 + c], B1 = pB[64 + c];
        int b  = m0 >> 12;               // m0 / 4096
        int ch = (m0 & 4095) >> 7;       // chunk within batch
        const size_t ci = ((size_t)(b * NCHUNK + ch)) * HDIM + n0 + c;
        g_A[ci] = A0 * A1;
        g_B[ci] = fmaf(A1, B0, B1);
    }
}

// ---------------- scan pass 3 (p2 folded in): rebuild prefix, emit outputs ---
__global__ void scan_p3(const float* __restrict__ h0, float* __restrict__ out)
{
    const int h  = (blockIdx.x * 128 + threadIdx.x) * 2;
    const int ch = blockIdx.y;
    const int b  = blockIdx.z;

    float2 x0 = *(const float2*)(h0 + b * HDIM + h);
    float h0c = gfun(x0.x), h1c = gfun(x0.y);
    for (int c = 0; c < ch; c++) {
        const size_t ci = ((size_t)(b * NCHUNK + c)) * HDIM + h;
        float2 Av = *(const float2*)(g_A + ci);
        float2 Bv = *(const float2*)(g_B + ci);
        h0c = fmaf(Av.x, h0c, Bv.x);
        h1c = fmaf(Av.y, h1c, Bv.y);
    }

    const size_t base = ((size_t)(b * S_LEN + ch * CHLEN)) * HDIM + h;
    const __half* zp = g_z + base;
    const __half* gp = g_g + base;
    float* op = out + base;
    for (int s0 = 0; s0 < CHLEN; s0 += 8) {
        __half2 zz[8], gg[8];
#pragma unroll
        for (int j = 0; j < 8; j++) {
            zz[j] = *(const __half2*)(zp + (size_t)(s0 + j) * HDIM);
            gg[j] = *(const __half2*)(gp + (size_t)(s0 + j) * HDIM);
        }
#pragma unroll
        for (int j = 0; j < 8; j++) {
            float2 zv = __half22float2(zz[j]);
            float2 gv = __half22float2(gg[j]);
            h0c = fmaf(zv.x, gv.x - h0c, h0c);
            h1c = fmaf(zv.y, gv.y - h1c, h1c);
            *(float2*)(op + (size_t)(s0 + j) * HDIM) = make_float2(h0c, h1c);
        }
    }
}

// ---------------- launch ------------------------------------------------------
extern "C" void kernel_launch(void* const* d_in, const int* in_sizes, int n_in,
                              void* d_out, int out_size)
{
    const float* x  = (const float*)d_in[0];
    const float* h0 = (const float*)d_in[1];
    const float* Wz = (const float*)d_in[2];
    const float* bz = (const float*)d_in[3];
    const float* Wh = (const float*)d_in[4];
    const float* bh = (const float*)d_in[5];
    float* out = (float*)d_out;

    convert_all<<<(X_N4 + 2 * W_N4 + 255) / 256, 256>>>(x, Wz, Wh);

    dim3 ggrid(HDIM / NT, MROWS / 128);   // (16, 256)
    gemm_mma<<<ggrid, 256>>>(bz, bh);

    dim3 sgrid(HDIM / 256, NCHUNK, BATCH);   // 2 channels per thread, 1024 CTAs
    scan_p3<<<sgrid, 128>>>(h0, out);
}